// round 3
// baseline (speedup 1.0000x reference)
#include <cuda_runtime.h>
#include <math.h>

#define D 128
#define MAXN 50000
#define MAXE 800000

// ---- persistent scratch (no allocation allowed) ----
__device__ float g_h[MAXN * D];     // current node features
__device__ float g_tmp[MAXN * D];   // h @ W
__device__ int   g_deg[MAXN];
__device__ float g_dinv[MAXN];
__device__ int   g_rowptr[MAXN + 1];
__device__ int   g_cursor[MAXN];
__device__ int   g_csr[MAXE];       // src node per CSR slot (grouped by dst)
__device__ int   g_ei64;            // 1 if edge_index is int64, 0 if int32
__device__ int   g_b64;             // 1 if batch is int64, 0 if int32

__device__ __forceinline__ int idx_at(const void* p, long long i, int is64) {
    return is64 ? (int)((const long long*)p)[i] : ((const int*)p)[i];
}

// ---------------------------------------------------------------------------
// dtype detection: sample first min(4096, cnt/2) entries as int64; any value
// outside [0, range) => buffer is int32. Samples stay within first cnt/2
// int64 slots = cnt*4 bytes, safe even if the buffer is int32-sized.
__global__ void k_detect(const void* ei, int Ecnt, int N,
                         const void* batch, int Bcnt, int G) {
    if (threadIdx.x != 0 || blockIdx.x != 0) return;
    {
        const long long* p = (const long long*)ei;
        int S = Ecnt / 2; if (S > 4096) S = 4096;
        int ok = 1;
        for (int i = 0; i < S; i++) {
            long long v = p[i];
            if (v < 0 || v >= N) { ok = 0; break; }
        }
        g_ei64 = ok;
    }
    {
        const long long* q = (const long long*)batch;
        int S = Bcnt / 2; if (S > 4096) S = 4096;
        int ok = 1;
        for (int i = 0; i < S; i++) {
            long long v = q[i];
            if (v < 0 || v >= G) { ok = 0; break; }
        }
        g_b64 = ok;
    }
}

// ---------------------------------------------------------------------------
__global__ void k_zero_deg(int n) {
    int i = blockIdx.x * blockDim.x + threadIdx.x;
    if (i < n) g_deg[i] = 0;
}

__global__ void k_count(const void* __restrict__ ei, int E, int N) {
    int e = blockIdx.x * blockDim.x + threadIdx.x;
    if (e < E) {
        int d = idx_at(ei, (long long)E + e, g_ei64);
        if (d >= 0 && d < N) atomicAdd(&g_deg[d], 1);
    }
}

__global__ void k_dinv(int n) {
    int i = blockIdx.x * blockDim.x + threadIdx.x;
    if (i < n) g_dinv[i] = rsqrtf((float)(g_deg[i] + 1));  // +1 self loop
}

// single-block scan over degrees -> rowptr, cursor
__global__ void k_scan(int n, int E) {
    __shared__ int part[1024];
    int t = threadIdx.x;
    int chunk = (n + 1023) >> 10;
    int base = t * chunk;
    int s = 0;
    for (int i = 0; i < chunk; i++) {
        int idx = base + i;
        if (idx < n) s += g_deg[idx];
    }
    part[t] = s;
    __syncthreads();
    for (int off = 1; off < 1024; off <<= 1) {
        int v = 0;
        if (t >= off) v = part[t - off];
        __syncthreads();
        part[t] += v;
        __syncthreads();
    }
    int run = (t > 0) ? part[t - 1] : 0;
    for (int i = 0; i < chunk; i++) {
        int idx = base + i;
        if (idx < n) {
            g_rowptr[idx] = run;
            g_cursor[idx] = run;
            run += g_deg[idx];
        }
    }
    if (t == 0) g_rowptr[n] = part[1023];
}

__global__ void k_scatter(const void* __restrict__ ei, int E, int N) {
    int e = blockIdx.x * blockDim.x + threadIdx.x;
    if (e < E) {
        int s = idx_at(ei, e, g_ei64);
        int d = idx_at(ei, (long long)E + e, g_ei64);
        if (s >= 0 && s < N && d >= 0 && d < N) {
            int p = atomicAdd(&g_cursor[d], 1);
            if (p >= 0 && p < E) g_csr[p] = s;
        }
    }
}

// ---------------------------------------------------------------------------
// g_tmp = A @ Wl   (A = X if useX else g_h), M x 128 @ 128 x 128
// 128x128 output tile per block, 256 threads, 8x8 per-thread microtile, BK=32
__global__ void __launch_bounds__(256) k_gemm(const float* __restrict__ X,
                                              const float* __restrict__ Wl,
                                              int M, int useX) {
    const float* A = useX ? X : g_h;
    __shared__ float sa[32][128];   // [k][m] (A transposed)
    __shared__ float sbuf[32][128]; // [k][n]
    int tid = threadIdx.x;
    int m0 = blockIdx.x * 128;
    int tx = tid & 15, ty = tid >> 4;

    float acc[8][8];
#pragma unroll
    for (int i = 0; i < 8; i++)
#pragma unroll
        for (int j = 0; j < 8; j++) acc[i][j] = 0.f;

    for (int kt = 0; kt < 4; kt++) {
        // W tile: 32 rows x 128 cols = 1024 float4
#pragma unroll
        for (int i = 0; i < 4; i++) {
            int lin = tid + 256 * i;
            int r = lin >> 5;     // k-row within tile
            int c4 = lin & 31;    // float4 column
            float4 v = ((const float4*)(Wl + (size_t)(kt * 32 + r) * 128))[c4];
            ((float4*)&sbuf[r][0])[c4] = v;
        }
        // A tile (transposed in smem): 128 rows x 32 k = 1024 float4
#pragma unroll
        for (int i = 0; i < 4; i++) {
            int lin = tid + 256 * i;
            int r = lin >> 3;     // m-row in tile
            int k4 = lin & 7;     // float4 within 32-k slab
            float4 v = make_float4(0.f, 0.f, 0.f, 0.f);
            int row = m0 + r;
            if (row < M) v = ((const float4*)(A + (size_t)row * 128 + kt * 32))[k4];
            int k = k4 * 4;
            sa[k][r] = v.x; sa[k + 1][r] = v.y; sa[k + 2][r] = v.z; sa[k + 3][r] = v.w;
        }
        __syncthreads();
#pragma unroll
        for (int k = 0; k < 32; k++) {
            float4 a0 = *((const float4*)&sa[k][ty * 8]);
            float4 a1 = *((const float4*)&sa[k][ty * 8 + 4]);
            float4 b0 = *((const float4*)&sbuf[k][tx * 8]);
            float4 b1 = *((const float4*)&sbuf[k][tx * 8 + 4]);
            float av[8] = {a0.x, a0.y, a0.z, a0.w, a1.x, a1.y, a1.z, a1.w};
            float bv[8] = {b0.x, b0.y, b0.z, b0.w, b1.x, b1.y, b1.z, b1.w};
#pragma unroll
            for (int i = 0; i < 8; i++)
#pragma unroll
                for (int j = 0; j < 8; j++) acc[i][j] += av[i] * bv[j];
        }
        __syncthreads();
    }
#pragma unroll
    for (int i = 0; i < 8; i++) {
        int row = m0 + ty * 8 + i;
        if (row < M) {
            float4 o0 = make_float4(acc[i][0], acc[i][1], acc[i][2], acc[i][3]);
            float4 o1 = make_float4(acc[i][4], acc[i][5], acc[i][6], acc[i][7]);
            ((float4*)(g_tmp + (size_t)row * 128))[tx * 2] = o0;
            ((float4*)(g_tmp + (size_t)row * 128))[tx * 2 + 1] = o1;
        }
    }
}

// ---------------------------------------------------------------------------
// gather aggregation: g_h[n] = relu( sum_{s in in(n)} tmp[s]*dinv[s]*dinv[n]
//                                   + tmp[n]*dinv[n]^2 + bias )
// one warp per node, float4 per lane (32 lanes * 4 = 128 features)
__global__ void __launch_bounds__(256) k_agg(const float* __restrict__ bias, int N, int E) {
    int wid = blockIdx.x * (blockDim.x >> 5) + (threadIdx.x >> 5);
    int lane = threadIdx.x & 31;
    if (wid >= N) return;
    float dn = g_dinv[wid];
    float4 v = ((const float4*)(g_tmp + (size_t)wid * D))[lane];
    float sc = dn * dn;
    float4 acc = make_float4(v.x * sc, v.y * sc, v.z * sc, v.w * sc);
    int beg = g_rowptr[wid], end = g_rowptr[wid + 1];
    if (beg < 0) beg = 0;
    if (end > E) end = E;
    for (int e = beg; e < end; e++) {
        int s = g_csr[e];
        float nr = g_dinv[s] * dn;
        float4 u = ((const float4*)(g_tmp + (size_t)s * D))[lane];
        acc.x += u.x * nr; acc.y += u.y * nr; acc.z += u.z * nr; acc.w += u.w * nr;
    }
    float4 bb = ((const float4*)bias)[lane];
    float4 r;
    r.x = fmaxf(acc.x + bb.x, 0.f);
    r.y = fmaxf(acc.y + bb.y, 0.f);
    r.z = fmaxf(acc.z + bb.z, 0.f);
    r.w = fmaxf(acc.w + bb.w, 0.f);
    ((float4*)(g_h + (size_t)wid * D))[lane] = r;
}

// ---------------------------------------------------------------------------
// mean pool per graph + linear head + log_softmax. one block per graph.
__global__ void k_pool(const void* __restrict__ batch,
                       const float* __restrict__ lin_w,
                       const float* __restrict__ lin_b,
                       float* hG_out, float* log_out,
                       int N, int nc) {
    int g = blockIdx.x, t = threadIdx.x;
    __shared__ int bounds[2];
    __shared__ float sh[D];
    __shared__ float sl[32];
    int is64 = g_b64;
    if (t == 0) {
        int lo = 0, hi = N;
        while (lo < hi) { int mid = (lo + hi) >> 1; if (idx_at(batch, mid, is64) < g) lo = mid + 1; else hi = mid; }
        bounds[0] = lo;
        hi = N;
        while (lo < hi) { int mid = (lo + hi) >> 1; if (idx_at(batch, mid, is64) <= g) lo = mid + 1; else hi = mid; }
        bounds[1] = lo;
    }
    __syncthreads();
    int beg = bounds[0], end = bounds[1];
    float sum = 0.f;
    for (int i = beg; i < end; i++) sum += g_h[(size_t)i * D + t];
    int c = end - beg;
    float cnt = (float)(c > 1 ? c : 1);
    float m = sum / cnt;
    if (hG_out) hG_out[(size_t)g * D + t] = m;
    sh[t] = m;
    __syncthreads();
    if (log_out) {
        if (t < nc) {
            float acc = lin_b[t];
            for (int k = 0; k < D; k++) acc += sh[k] * lin_w[k * nc + t];
            sl[t] = acc;
        }
        __syncthreads();
        if (t == 0) {
            float mx = -1e30f;
            for (int j = 0; j < nc; j++) mx = fmaxf(mx, sl[j]);
            float se = 0.f;
            for (int j = 0; j < nc; j++) se += expf(sl[j] - mx);
            float lse = mx + logf(se);
            for (int j = 0; j < nc; j++) log_out[(size_t)g * nc + j] = sl[j] - lse;
        }
    }
}

// ---------------------------------------------------------------------------
extern "C" void kernel_launch(void* const* d_in, const int* in_sizes, int n_in,
                              void* d_out, int out_size) {
    // Identify inputs by (distinct) element counts; fall back to position.
    const float* x = (const float*)d_in[0];
    const float* W = (const float*)d_in[1];
    const float* b = (const float*)d_in[2];
    const float* lin_w = (const float*)d_in[3];
    const float* lin_b = (const float*)d_in[4];
    const void* ei = d_in[5];
    const void* batch = d_in[6];
    int sz_x = in_sizes[0], sz_W = in_sizes[1], sz_lb = in_sizes[4],
        sz_ei = in_sizes[5], sz_batch = in_sizes[6];
    for (int i = 0; i < n_in; i++) {
        int s = in_sizes[i];
        switch (s) {
            case 6400000: x = (const float*)d_in[i]; sz_x = s; break;       // N*D
            case 49152:   W = (const float*)d_in[i]; sz_W = s; break;       // L*D*D
            case 384:     b = (const float*)d_in[i]; break;                 // L*D
            case 1280:    lin_w = (const float*)d_in[i]; break;             // D*nc
            case 10:      lin_b = (const float*)d_in[i]; sz_lb = s; break;  // nc
            case 1600000: ei = d_in[i]; sz_ei = s; break;                   // 2*E
            case 50000:   batch = d_in[i]; sz_batch = s; break;             // N
            default: break;
        }
    }

    int N = sz_x / D;
    int E = sz_ei / 2;
    int L = sz_W / (D * D);
    int nc = sz_lb;

    float* out = (float*)d_out;
    float* hG_out = 0;
    float* log_out = 0;
    int G = 0;
    if (out_size % (D + nc) == 0) {     // concatenated (hG, log_softmax)
        G = out_size / (D + nc);
        hG_out = out;
        log_out = out + (size_t)G * D;
    } else if (out_size % D == 0) {     // hG only
        G = out_size / D;
        hG_out = out;
    } else {                            // logits only
        G = out_size / nc;
        log_out = out;
    }

    int tE = (E + 255) / 256;
    int tN = (N + 255) / 256;

    k_detect<<<1, 32>>>(ei, sz_ei, N, batch, sz_batch, G);
    k_zero_deg<<<tN, 256>>>(N);
    k_count<<<tE, 256>>>(ei, E, N);
    k_dinv<<<tN, 256>>>(N);
    k_scan<<<1, 1024>>>(N, E);
    k_scatter<<<tE, 256>>>(ei, E, N);

    int gemm_blocks = (N + 127) / 128;
    int agg_blocks = (N + 7) / 8;       // 8 warps/block, warp per node
    for (int l = 0; l < L; l++) {
        k_gemm<<<gemm_blocks, 256>>>(x, W + (size_t)l * D * D, N, l == 0 ? 1 : 0);
        k_agg<<<agg_blocks, 256>>>(b + (size_t)l * D, N, E);
    }
    k_pool<<<G, D>>>(batch, lin_w, lin_b, hG_out, log_out, N, nc);
}

// round 6
// speedup vs baseline: 1.0286x; 1.0286x over previous
#include <cuda_runtime.h>
#include <math.h>

#define D 128
#define MAXN 50000
#define MAXE 800000

// ---- persistent scratch (no allocation allowed) ----
__device__ float g_h[MAXN * D];     // current node features
__device__ float g_tmp[MAXN * D];   // (h @ W) * dinv[row]  (pre-scaled)
__device__ int   g_deg[MAXN];
__device__ float g_dinv[MAXN];
__device__ int   g_rowptr[MAXN + 1];
__device__ int   g_cursor[MAXN];
__device__ int   g_csr[MAXE];       // src node per CSR slot (grouped by dst)
__device__ int   g_ei64;            // 1 if edge_index is int64, 0 if int32
__device__ int   g_b64;             // 1 if batch is int64, 0 if int32

__device__ __forceinline__ int idx_at(const void* p, long long i, int is64) {
    return is64 ? (int)((const long long*)p)[i] : ((const int*)p)[i];
}

// ---------------------------------------------------------------------------
__global__ void k_flags_init() { g_ei64 = 1; g_b64 = 1; }

// Parallel dtype detection: interpret first cnt/2 entries as int64; any value
// outside [0, range) => buffer is int32 (atomicAnd clears flag). Sampling
// stays within cnt*4 bytes, safe even if the buffer is int32-sized.
__global__ void k_detect(const void* __restrict__ buf, int cnt, int range, int which) {
    const long long* p = (const long long*)buf;
    int S = cnt / 2; if (S > 8192) S = 8192;
    int bad = 0;
    for (int i = blockIdx.x * blockDim.x + threadIdx.x; i < S;
         i += gridDim.x * blockDim.x) {
        long long v = p[i];
        if (v < 0 || v >= range) bad = 1;
    }
    if (__syncthreads_or(bad)) {
        if (threadIdx.x == 0) {
            if (which == 0) atomicAnd(&g_ei64, 0);
            else            atomicAnd(&g_b64, 0);
        }
    }
}

// ---------------------------------------------------------------------------
__global__ void k_zero_deg(int n) {
    int i = blockIdx.x * blockDim.x + threadIdx.x;
    if (i < n) g_deg[i] = 0;
}

__global__ void k_count(const void* __restrict__ ei, int E, int N) {
    int e = blockIdx.x * blockDim.x + threadIdx.x;
    if (e < E) {
        int d = idx_at(ei, (long long)E + e, g_ei64);
        if (d >= 0 && d < N) atomicAdd(&g_deg[d], 1);
    }
}

__global__ void k_dinv(int n) {
    int i = blockIdx.x * blockDim.x + threadIdx.x;
    if (i < n) g_dinv[i] = rsqrtf((float)(g_deg[i] + 1));  // +1 self loop
}

// single-block scan over degrees -> rowptr, cursor
__global__ void k_scan(int n, int E) {
    __shared__ int part[1024];
    int t = threadIdx.x;
    int chunk = (n + 1023) >> 10;
    int base = t * chunk;
    int s = 0;
    for (int i = 0; i < chunk; i++) {
        int idx = base + i;
        if (idx < n) s += g_deg[idx];
    }
    part[t] = s;
    __syncthreads();
    for (int off = 1; off < 1024; off <<= 1) {
        int v = 0;
        if (t >= off) v = part[t - off];
        __syncthreads();
        part[t] += v;
        __syncthreads();
    }
    int run = (t > 0) ? part[t - 1] : 0;
    for (int i = 0; i < chunk; i++) {
        int idx = base + i;
        if (idx < n) {
            g_rowptr[idx] = run;
            g_cursor[idx] = run;
            run += g_deg[idx];
        }
    }
    if (t == 0) g_rowptr[n] = part[1023];
}

__global__ void k_scatter(const void* __restrict__ ei, int E, int N) {
    int e = blockIdx.x * blockDim.x + threadIdx.x;
    if (e < E) {
        int s = idx_at(ei, e, g_ei64);
        int d = idx_at(ei, (long long)E + e, g_ei64);
        if (s >= 0 && s < N && d >= 0 && d < N) {
            int p = atomicAdd(&g_cursor[d], 1);
            if (p >= 0 && p < E) g_csr[p] = s;
        }
    }
}

// ---------------------------------------------------------------------------
// g_tmp = (A @ Wl) * dinv[row]   (A = X if useX else g_h), M x 128 @ 128 x 128
// 128x128 output tile per block, 256 threads, 8x8 per-thread microtile, BK=32
__global__ void __launch_bounds__(256) k_gemm(const float* __restrict__ X,
                                              const float* __restrict__ Wl,
                                              int M, int useX) {
    const float* A = useX ? X : g_h;
    __shared__ float sa[32][128];   // [k][m] (A transposed)
    __shared__ float sbuf[32][128]; // [k][n]
    int tid = threadIdx.x;
    int m0 = blockIdx.x * 128;
    int tx = tid & 15, ty = tid >> 4;

    float acc[8][8];
#pragma unroll
    for (int i = 0; i < 8; i++)
#pragma unroll
        for (int j = 0; j < 8; j++) acc[i][j] = 0.f;

    for (int kt = 0; kt < 4; kt++) {
        // W tile: 32 rows x 128 cols = 1024 float4
#pragma unroll
        for (int i = 0; i < 4; i++) {
            int lin = tid + 256 * i;
            int r = lin >> 5;     // k-row within tile
            int c4 = lin & 31;    // float4 column
            float4 v = ((const float4*)(Wl + (size_t)(kt * 32 + r) * 128))[c4];
            ((float4*)&sbuf[r][0])[c4] = v;
        }
        // A tile (transposed in smem): 128 rows x 32 k = 1024 float4
#pragma unroll
        for (int i = 0; i < 4; i++) {
            int lin = tid + 256 * i;
            int r = lin >> 3;     // m-row in tile
            int k4 = lin & 7;     // float4 within 32-k slab
            float4 v = make_float4(0.f, 0.f, 0.f, 0.f);
            int row = m0 + r;
            if (row < M) v = ((const float4*)(A + (size_t)row * 128 + kt * 32))[k4];
            int k = k4 * 4;
            sa[k][r] = v.x; sa[k + 1][r] = v.y; sa[k + 2][r] = v.z; sa[k + 3][r] = v.w;
        }
        __syncthreads();
#pragma unroll
        for (int k = 0; k < 32; k++) {
            float4 a0 = *((const float4*)&sa[k][ty * 8]);
            float4 a1 = *((const float4*)&sa[k][ty * 8 + 4]);
            float4 b0 = *((const float4*)&sbuf[k][tx * 8]);
            float4 b1 = *((const float4*)&sbuf[k][tx * 8 + 4]);
            float av[8] = {a0.x, a0.y, a0.z, a0.w, a1.x, a1.y, a1.z, a1.w};
            float bv[8] = {b0.x, b0.y, b0.z, b0.w, b1.x, b1.y, b1.z, b1.w};
#pragma unroll
            for (int i = 0; i < 8; i++)
#pragma unroll
                for (int j = 0; j < 8; j++) acc[i][j] += av[i] * bv[j];
        }
        __syncthreads();
    }
#pragma unroll
    for (int i = 0; i < 8; i++) {
        int row = m0 + ty * 8 + i;
        if (row < M) {
            float dv = g_dinv[row];
            float4 o0 = make_float4(acc[i][0] * dv, acc[i][1] * dv,
                                    acc[i][2] * dv, acc[i][3] * dv);
            float4 o1 = make_float4(acc[i][4] * dv, acc[i][5] * dv,
                                    acc[i][6] * dv, acc[i][7] * dv);
            ((float4*)(g_tmp + (size_t)row * 128))[tx * 2] = o0;
            ((float4*)(g_tmp + (size_t)row * 128))[tx * 2 + 1] = o1;
        }
    }
}

// ---------------------------------------------------------------------------
// gather aggregation with pre-scaled tmp' = tmp*dinv:
// g_h[n] = relu( (tmp'[n] + sum_{s in in(n)} tmp'[s]) * dinv[n] + bias )
// one warp per node, float4 per lane (32 lanes * 4 = 128 features)
__global__ void __launch_bounds__(256) k_agg(const float* __restrict__ bias, int N, int E) {
    int wid = blockIdx.x * (blockDim.x >> 5) + (threadIdx.x >> 5);
    int lane = threadIdx.x & 31;
    if (wid >= N) return;
    float dn = g_dinv[wid];
    float4 acc = ((const float4*)(g_tmp + (size_t)wid * D))[lane];  // self term
    int beg = g_rowptr[wid], end = g_rowptr[wid + 1];
    if (beg < 0) beg = 0;
    if (end > E) end = E;
#pragma unroll 4
    for (int e = beg; e < end; e++) {
        int s = g_csr[e];
        float4 u = ((const float4*)(g_tmp + (size_t)s * D))[lane];
        acc.x += u.x; acc.y += u.y; acc.z += u.z; acc.w += u.w;
    }
    float4 bb = ((const float4*)bias)[lane];
    float4 r;
    r.x = fmaxf(fmaf(acc.x, dn, bb.x), 0.f);
    r.y = fmaxf(fmaf(acc.y, dn, bb.y), 0.f);
    r.z = fmaxf(fmaf(acc.z, dn, bb.z), 0.f);
    r.w = fmaxf(fmaf(acc.w, dn, bb.w), 0.f);
    ((float4*)(g_h + (size_t)wid * D))[lane] = r;
}

// ---------------------------------------------------------------------------
// mean pool per graph + linear head + log_softmax. one block per graph.
__global__ void k_pool(const void* __restrict__ batch,
                       const float* __restrict__ lin_w,
                       const float* __restrict__ lin_b,
                       float* hG_out, float* log_out,
                       int N, int nc) {
    int g = blockIdx.x, t = threadIdx.x;
    __shared__ int bounds[2];
    __shared__ float sh[D];
    __shared__ float sl[32];
    int is64 = g_b64;
    if (t == 0) {
        int lo = 0, hi = N;
        while (lo < hi) { int mid = (lo + hi) >> 1; if (idx_at(batch, mid, is64) < g) lo = mid + 1; else hi = mid; }
        bounds[0] = lo;
        hi = N;
        while (lo < hi) { int mid = (lo + hi) >> 1; if (idx_at(batch, mid, is64) <= g) lo = mid + 1; else hi = mid; }
        bounds[1] = lo;
    }
    __syncthreads();
    int beg = bounds[0], end = bounds[1];
    float sum = 0.f;
    for (int i = beg; i < end; i++) sum += g_h[(size_t)i * D + t];
    int c = end - beg;
    float cnt = (float)(c > 1 ? c : 1);
    float m = sum / cnt;
    if (hG_out) hG_out[(size_t)g * D + t] = m;
    sh[t] = m;
    __syncthreads();
    if (log_out) {
        if (t < nc) {
            float acc = lin_b[t];
            for (int k = 0; k < D; k++) acc += sh[k] * lin_w[k * nc + t];
            sl[t] = acc;
        }
        __syncthreads();
        if (t == 0) {
            float mx = -1e30f;
            for (int j = 0; j < nc; j++) mx = fmaxf(mx, sl[j]);
            float se = 0.f;
            for (int j = 0; j < nc; j++) se += expf(sl[j] - mx);
            float lse = mx + logf(se);
            for (int j = 0; j < nc; j++) log_out[(size_t)g * nc + j] = sl[j] - lse;
        }
    }
}

// ---------------------------------------------------------------------------
extern "C" void kernel_launch(void* const* d_in, const int* in_sizes, int n_in,
                              void* d_out, int out_size) {
    // Identify inputs by (distinct) element counts; fall back to position.
    const float* x = (const float*)d_in[0];
    const float* W = (const float*)d_in[1];
    const float* b = (const float*)d_in[2];
    const float* lin_w = (const float*)d_in[3];
    const float* lin_b = (const float*)d_in[4];
    const void* ei = d_in[5];
    const void* batch = d_in[6];
    int sz_x = in_sizes[0], sz_W = in_sizes[1], sz_lb = in_sizes[4],
        sz_ei = in_sizes[5], sz_batch = in_sizes[6];
    for (int i = 0; i < n_in; i++) {
        int s = in_sizes[i];
        switch (s) {
            case 6400000: x = (const float*)d_in[i]; sz_x = s; break;       // N*D
            case 49152:   W = (const float*)d_in[i]; sz_W = s; break;       // L*D*D
            case 384:     b = (const float*)d_in[i]; break;                 // L*D
            case 1280:    lin_w = (const float*)d_in[i]; break;             // D*nc
            case 10:      lin_b = (const float*)d_in[i]; sz_lb = s; break;  // nc
            case 1600000: ei = d_in[i]; sz_ei = s; break;                   // 2*E
            case 50000:   batch = d_in[i]; sz_batch = s; break;             // N
            default: break;
        }
    }

    int N = sz_x / D;
    int E = sz_ei / 2;
    int L = sz_W / (D * D);
    int nc = sz_lb;

    float* out = (float*)d_out;
    float* hG_out = 0;
    float* log_out = 0;
    int G = 0;
    if (out_size % (D + nc) == 0) {     // concatenated (hG, log_softmax)
        G = out_size / (D + nc);
        hG_out = out;
        log_out = out + (size_t)G * D;
    } else if (out_size % D == 0) {     // hG only
        G = out_size / D;
        hG_out = out;
    } else {                            // logits only
        G = out_size / nc;
        log_out = out;
    }

    int tE = (E + 255) / 256;
    int tN = (N + 255) / 256;

    k_flags_init<<<1, 1>>>();
    k_detect<<<16, 256>>>(ei, sz_ei, N, 0);
    k_detect<<<16, 256>>>(batch, sz_batch, G, 1);
    k_zero_deg<<<tN, 256>>>(N);
    k_count<<<tE, 256>>>(ei, E, N);
    k_dinv<<<tN, 256>>>(N);
    k_scan<<<1, 1024>>>(N, E);
    k_scatter<<<tE, 256>>>(ei, E, N);

    int gemm_blocks = (N + 127) / 128;
    int agg_blocks = (N + 7) / 8;       // 8 warps/block, warp per node
    for (int l = 0; l < L; l++) {
        k_gemm<<<gemm_blocks, 256>>>(x, W + (size_t)l * D * D, N, l == 0 ? 1 : 0);
        k_agg<<<agg_blocks, 256>>>(b + (size_t)l * D, N, E);
    }
    k_pool<<<G, D>>>(batch, lin_w, lin_b, hG_out, log_out, N, nc);
}